// round 1
// baseline (speedup 1.0000x reference)
#include <cuda_runtime.h>
#include <math.h>

#define B 32
#define DIN 2048
#define D 128
#define NREPS 400000
#define ADIM 7
#define KSEL 5

#define GRID_MAIN 304
#define TILE_N 64
#define NTILES (NREPS / TILE_N)   /* 6250, exact */
#define P2 66                     /* padded float2 pitch of rp rows: 528B = 16*33 */
#define CAND_PER_B 160            /* 32 lanes * 5 */

typedef unsigned long long u64;

/* ---------------- device scratch (no allocations allowed) ---------------- */
__device__ float g_batch[B * D];
__device__ float g_anorm[B];
__device__ float g_ckey[GRID_MAIN * B * CAND_PER_B];
__device__ int   g_cidx[GRID_MAIN * B * CAND_PER_B];

/* ---------------- packed f32x2 helpers ---------------- */
__device__ __forceinline__ u64 ffma2(u64 a, u64 b, u64 c) {
    u64 d;
    asm("fma.rn.f32x2 %0, %1, %2, %3;" : "=l"(d) : "l"(a), "l"(b), "l"(c));
    return d;
}
__device__ __forceinline__ float f2sum(u64 p) {
    float lo, hi;
    asm("mov.b64 {%0, %1}, %2;" : "=f"(lo), "=f"(hi) : "l"(p));
    return lo + hi;
}

/* ================= encoder: batch_rep = x @ W_enc + b_enc ================= */
__global__ void enc_kernel(const float* __restrict__ x,
                           const float* __restrict__ W,
                           const float* __restrict__ bias) {
    __shared__ float xs[DIN];
    __shared__ float red[4];
    int b = blockIdx.x, t = threadIdx.x;   /* 128 threads, t = output dim */
    for (int i = t; i < DIN; i += 128) xs[i] = x[b * DIN + i];
    __syncthreads();
    float acc = 0.f;
#pragma unroll 8
    for (int d = 0; d < DIN; d++) acc = fmaf(xs[d], W[d * D + t], acc);
    float r = acc + bias[t];
    g_batch[b * D + t] = r;
    float sq = r * r;
#pragma unroll
    for (int o = 16; o > 0; o >>= 1) sq += __shfl_down_sync(0xffffffffu, sq, o);
    if ((t & 31) == 0) red[t >> 5] = sq;
    __syncthreads();
    if (t == 0) g_anorm[b] = red[0] + red[1] + red[2] + red[3];
}

/* ================= main: keys + per-lane top-5 ================= */
__global__ void __launch_bounds__(256, 2) dist_kernel(const float* __restrict__ reps) {
    extern __shared__ char smem[];
    float2* rp = (float2*)smem;                                   /* [64][P2]  reps pairs, transposed */
    float2* bp = (float2*)(smem + 64 * P2 * 8);                   /* [64][32]  batch pairs */
    float*  npart = (float*)(smem + 64 * P2 * 8 + 64 * 32 * 8);   /* [4][64] */
    float*  normsh = npart + 4 * 64;                              /* [64] */

    int t = threadIdx.x;
    int w = t >> 5, lane = t & 31;
    int b0 = w * 4;          /* warp owns batch rows b0..b0+3 */
    int n0 = lane * 2;       /* lane owns tile cols n0, n0+1 */

    /* pack batch_rep into bp[dp][b] = (batch[b][2dp], batch[b][2dp+1]) */
    for (int i = t; i < 64 * 32; i += 256) {
        int dp = i >> 5, b = i & 31;
        bp[dp * 32 + b] = make_float2(g_batch[b * D + 2 * dp], g_batch[b * D + 2 * dp + 1]);
    }
    __syncthreads();

    float tk[4][5]; int tn[4][5];
#pragma unroll
    for (int bi = 0; bi < 4; bi++)
#pragma unroll
        for (int j = 0; j < 5; j++) { tk[bi][j] = 3.0e38f; tn[bi][j] = 0; }

    const float2* reps2 = (const float2*)reps;

    for (int tile = blockIdx.x; tile < NTILES; tile += gridDim.x) {
        int tb = tile * TILE_N;

        /* ---- stage tile, transposed: rp[dp][n]; STS.128 conflict-free per phase ---- */
#pragma unroll
        for (int pi = 0; pi < 4; pi++) {
            int p = w + pi * 8;              /* row pair index 0..31 */
            int r0 = tb + 2 * p;
#pragma unroll
            for (int half = 0; half < 2; half++) {
                int dp = half * 32 + lane;
                float2 a0 = reps2[r0 * 64 + dp];
                float2 a1 = reps2[(r0 + 1) * 64 + dp];
                *(float4*)&rp[dp * P2 + 2 * p] = make_float4(a0.x, a0.y, a1.x, a1.y);
            }
        }
        __syncthreads();   /* stage done */

        /* ---- per-tile row norms (partial): conflict-free LDS ---- */
        {
            int n = t & 63, h = t >> 6;
            float s = 0.f;
#pragma unroll
            for (int j = 0; j < 16; j++) {
                float2 v = rp[(h * 16 + j) * P2 + n];
                s = fmaf(v.x, v.x, fmaf(v.y, v.y, s));
            }
            npart[h * 64 + n] = s;
        }

        /* ---- main dot accumulation: 8 FFMA2 + 3 LDS.128 per d-pair ---- */
        u64 acc[4][2];
#pragma unroll
        for (int bi = 0; bi < 4; bi++) { acc[bi][0] = 0ull; acc[bi][1] = 0ull; }

        const char* bptr = (const char*)(bp + b0);
        const char* rptr = (const char*)(rp + n0);
#pragma unroll 8
        for (int dp = 0; dp < 64; dp++) {
            ulonglong2 bu01 = *(const ulonglong2*)(bptr);        /* b0,b1 (broadcast) */
            ulonglong2 bu23 = *(const ulonglong2*)(bptr + 16);   /* b2,b3 (broadcast) */
            ulonglong2 ru   = *(const ulonglong2*)(rptr);        /* n0,n0+1 */
            acc[0][0] = ffma2(bu01.x, ru.x, acc[0][0]);
            acc[0][1] = ffma2(bu01.x, ru.y, acc[0][1]);
            acc[1][0] = ffma2(bu01.y, ru.x, acc[1][0]);
            acc[1][1] = ffma2(bu01.y, ru.y, acc[1][1]);
            acc[2][0] = ffma2(bu23.x, ru.x, acc[2][0]);
            acc[2][1] = ffma2(bu23.x, ru.y, acc[2][1]);
            acc[3][0] = ffma2(bu23.y, ru.x, acc[3][0]);
            acc[3][1] = ffma2(bu23.y, ru.y, acc[3][1]);
            bptr += 32 * 8;
            rptr += P2 * 8;
        }
        __syncthreads();   /* npart complete, rp reads complete */
        if (t < 64) normsh[t] = npart[t] + npart[64 + t] + npart[128 + t] + npart[192 + t];
        __syncthreads();   /* normsh ready */

        /* ---- key = ||r||^2 - 2 a.r ; per-lane sorted top-5 per b ---- */
#pragma unroll
        for (int nj = 0; nj < 2; nj++) {
            float nn = normsh[n0 + nj];
            int ng = tb + n0 + nj;
#pragma unroll
            for (int bi = 0; bi < 4; bi++) {
                float key = nn - 2.0f * f2sum(acc[bi][nj]);
                if (key < tk[bi][4]) {
                    tk[bi][4] = key; tn[bi][4] = ng;
#pragma unroll
                    for (int j = 4; j > 0; j--) {
                        if (tk[bi][j] < tk[bi][j - 1]) {
                            float fk = tk[bi][j]; tk[bi][j] = tk[bi][j - 1]; tk[bi][j - 1] = fk;
                            int ii = tn[bi][j]; tn[bi][j] = tn[bi][j - 1]; tn[bi][j - 1] = ii;
                        }
                    }
                }
            }
        }
        /* next-tile restage is safe: every thread passed the norm barriers above */
    }

    /* ---- emit candidates ---- */
#pragma unroll
    for (int bi = 0; bi < 4; bi++) {
        int b = b0 + bi;
        int base = (blockIdx.x * B + b) * CAND_PER_B + lane * 5;
#pragma unroll
        for (int j = 0; j < 5; j++) {
            g_ckey[base + j] = tk[bi][j];
            g_cidx[base + j] = tn[bi][j];
        }
    }
}

/* ================= final: merge candidates, softmax, gather actions ================= */
__global__ void final_kernel(const float* __restrict__ actions, float* __restrict__ out) {
    __shared__ float skey[256 * 5];
    __shared__ int   sidx[256 * 5];
    __shared__ float skey2[32 * 5];
    __shared__ int   sidx2[32 * 5];
    int b = blockIdx.x, t = threadIdx.x;

    float tk[5]; int tn[5];
#pragma unroll
    for (int j = 0; j < 5; j++) { tk[j] = 3.0e38f; tn[j] = 0; }

    const int total = GRID_MAIN * CAND_PER_B;
    for (int i = t; i < total; i += 256) {
        int g = i / CAND_PER_B, r = i - g * CAND_PER_B;
        int addr = (g * B + b) * CAND_PER_B + r;
        float key = g_ckey[addr];
        if (key < tk[4]) {
            int idx = g_cidx[addr];
            tk[4] = key; tn[4] = idx;
#pragma unroll
            for (int j = 4; j > 0; j--) {
                if (tk[j] < tk[j - 1]) {
                    float fk = tk[j]; tk[j] = tk[j - 1]; tk[j - 1] = fk;
                    int ii = tn[j]; tn[j] = tn[j - 1]; tn[j - 1] = ii;
                }
            }
        }
    }
#pragma unroll
    for (int j = 0; j < 5; j++) { skey[t * 5 + j] = tk[j]; sidx[t * 5 + j] = tn[j]; }
    __syncthreads();

    /* stage 2: 32 threads each merge 8 lists of 5 */
    if (t < 32) {
        float fk[5]; int fn[5];
#pragma unroll
        for (int j = 0; j < 5; j++) { fk[j] = 3.0e38f; fn[j] = 0; }
        for (int i = t * 40; i < t * 40 + 40; i++) {
            float key = skey[i];
            if (key < fk[4]) {
                int idx = sidx[i];
                fk[4] = key; fn[4] = idx;
#pragma unroll
                for (int j = 4; j > 0; j--) {
                    if (fk[j] < fk[j - 1]) {
                        float a2 = fk[j]; fk[j] = fk[j - 1]; fk[j - 1] = a2;
                        int i2 = fn[j]; fn[j] = fn[j - 1]; fn[j - 1] = i2;
                    }
                }
            }
        }
#pragma unroll
        for (int j = 0; j < 5; j++) { skey2[t * 5 + j] = fk[j]; sidx2[t * 5 + j] = fn[j]; }
    }
    __syncthreads();

    if (t == 0) {
        float fk[5]; int fn[5];
#pragma unroll
        for (int j = 0; j < 5; j++) { fk[j] = 3.0e38f; fn[j] = 0; }
        for (int i = 0; i < 32 * 5; i++) {
            float key = skey2[i];
            if (key < fk[4]) {
                int idx = sidx2[i];
                fk[4] = key; fn[4] = idx;
#pragma unroll
                for (int j = 4; j > 0; j--) {
                    if (fk[j] < fk[j - 1]) {
                        float a2 = fk[j]; fk[j] = fk[j - 1]; fk[j - 1] = a2;
                        int i2 = fn[j]; fn[j] = fn[j - 1]; fn[j - 1] = i2;
                    }
                }
            }
        }
        float an = g_anorm[b];
        float dloc[5];
        float dmin = 3.0e38f;
#pragma unroll
        for (int j = 0; j < KSEL; j++) {
            dloc[j] = sqrtf(fmaxf(an + fk[j], 1e-12f));
            dmin = fminf(dmin, dloc[j]);
        }
        float wsum = 0.f;
        float pred[ADIM];
#pragma unroll
        for (int a = 0; a < ADIM; a++) pred[a] = 0.f;
#pragma unroll
        for (int j = 0; j < KSEL; j++) {
            float wgt = expf(-(dloc[j] - dmin));
            wsum += wgt;
            const float* arow = actions + (size_t)fn[j] * ADIM;
#pragma unroll
            for (int a = 0; a < ADIM; a++) pred[a] = fmaf(wgt, arow[a], pred[a]);
        }
        float inv = 1.0f / wsum;
#pragma unroll
        for (int a = 0; a < ADIM; a++) out[b * ADIM + a] = pred[a] * inv;
    }
}

/* ================= launch ================= */
extern "C" void kernel_launch(void* const* d_in, const int* in_sizes, int n_in,
                              void* d_out, int out_size) {
    (void)in_sizes; (void)n_in; (void)out_size;
    const float* x       = (const float*)d_in[0];
    const float* W       = (const float*)d_in[1];
    const float* bias    = (const float*)d_in[2];
    const float* reps    = (const float*)d_in[3];
    const float* actions = (const float*)d_in[4];
    float* out = (float*)d_out;

    const int smem_bytes = 64 * P2 * 8 + 64 * 32 * 8 + 4 * 64 * 4 + 64 * 4; /* 51456 */
    cudaFuncSetAttribute(dist_kernel, cudaFuncAttributeMaxDynamicSharedMemorySize, smem_bytes);

    enc_kernel<<<B, 128>>>(x, W, bias);
    dist_kernel<<<GRID_MAIN, 256, smem_bytes>>>(reps);
    final_kernel<<<B, 256>>>(actions, out);
}

// round 2
// speedup vs baseline: 1.0008x; 1.0008x over previous
#include <cuda_runtime.h>
#include <math.h>

#define B 32
#define DIN 2048
#define D 128
#define NREPS 400000
#define ADIM 7
#define KSEL 5

#define GRID_MAIN 304
#define TILE_N 64
#define NTILES (NREPS / TILE_N)   /* 6250, exact */
#define P2 66                     /* padded float2 pitch of rp rows: 528B = 16*33 */
#define CAND_PER_B 160            /* 32 lanes * 5 */

typedef unsigned long long u64;

/* ---------------- device scratch (no allocations allowed) ---------------- */
__device__ float g_batch[B * D];
__device__ float g_anorm[B];
__device__ float g_ckey[GRID_MAIN * B * CAND_PER_B];
__device__ int   g_cidx[GRID_MAIN * B * CAND_PER_B];

/* ---------------- packed f32x2 helpers ---------------- */
__device__ __forceinline__ u64 ffma2(u64 a, u64 b, u64 c) {
    u64 d;
    asm("fma.rn.f32x2 %0, %1, %2, %3;" : "=l"(d) : "l"(a), "l"(b), "l"(c));
    return d;
}
__device__ __forceinline__ float f2sum(u64 p) {
    float lo, hi;
    asm("mov.b64 {%0, %1}, %2;" : "=f"(lo), "=f"(hi) : "l"(p));
    return lo + hi;
}

/* ================= encoder: batch_rep = x @ W_enc + b_enc ================= */
__global__ void enc_kernel(const float* __restrict__ x,
                           const float* __restrict__ W,
                           const float* __restrict__ bias) {
    __shared__ float xs[DIN];
    __shared__ float red[4];
    int b = blockIdx.x, t = threadIdx.x;   /* 128 threads, t = output dim */
    for (int i = t; i < DIN; i += 128) xs[i] = x[b * DIN + i];
    __syncthreads();
    float acc = 0.f;
#pragma unroll 8
    for (int d = 0; d < DIN; d++) acc = fmaf(xs[d], W[d * D + t], acc);
    float r = acc + bias[t];
    g_batch[b * D + t] = r;
    float sq = r * r;
#pragma unroll
    for (int o = 16; o > 0; o >>= 1) sq += __shfl_down_sync(0xffffffffu, sq, o);
    if ((t & 31) == 0) red[t >> 5] = sq;
    __syncthreads();
    if (t == 0) g_anorm[b] = red[0] + red[1] + red[2] + red[3];
}

/* ================= main: keys + per-lane top-5 ================= */
__global__ void __launch_bounds__(256, 2) dist_kernel(const float* __restrict__ reps) {
    extern __shared__ char smem[];
    float2* rp = (float2*)smem;                                   /* [64][P2]  reps pairs, transposed */
    float2* bp = (float2*)(smem + 64 * P2 * 8);                   /* [64][32]  batch pairs */
    float*  npart = (float*)(smem + 64 * P2 * 8 + 64 * 32 * 8);   /* [4][64] */
    float*  normsh = npart + 4 * 64;                              /* [64] */

    int t = threadIdx.x;
    int w = t >> 5, lane = t & 31;
    int b0 = w * 4;          /* warp owns batch rows b0..b0+3 */
    int n0 = lane * 2;       /* lane owns tile cols n0, n0+1 */

    /* pack batch_rep into bp[dp][b] = (batch[b][2dp], batch[b][2dp+1]) */
    for (int i = t; i < 64 * 32; i += 256) {
        int dp = i >> 5, b = i & 31;
        bp[dp * 32 + b] = make_float2(g_batch[b * D + 2 * dp], g_batch[b * D + 2 * dp + 1]);
    }
    __syncthreads();

    float tk[4][5]; int tn[4][5];
#pragma unroll
    for (int bi = 0; bi < 4; bi++)
#pragma unroll
        for (int j = 0; j < 5; j++) { tk[bi][j] = 3.0e38f; tn[bi][j] = 0; }

    const float2* reps2 = (const float2*)reps;

    for (int tile = blockIdx.x; tile < NTILES; tile += gridDim.x) {
        int tb = tile * TILE_N;

        /* ---- stage tile, transposed: rp[dp][n]; STS.128 conflict-free per phase ---- */
#pragma unroll
        for (int pi = 0; pi < 4; pi++) {
            int p = w + pi * 8;              /* row pair index 0..31 */
            int r0 = tb + 2 * p;
#pragma unroll
            for (int half = 0; half < 2; half++) {
                int dp = half * 32 + lane;
                float2 a0 = reps2[r0 * 64 + dp];
                float2 a1 = reps2[(r0 + 1) * 64 + dp];
                *(float4*)&rp[dp * P2 + 2 * p] = make_float4(a0.x, a0.y, a1.x, a1.y);
            }
        }
        __syncthreads();   /* stage done */

        /* ---- per-tile row norms (partial): conflict-free LDS ---- */
        {
            int n = t & 63, h = t >> 6;
            float s = 0.f;
#pragma unroll
            for (int j = 0; j < 16; j++) {
                float2 v = rp[(h * 16 + j) * P2 + n];
                s = fmaf(v.x, v.x, fmaf(v.y, v.y, s));
            }
            npart[h * 64 + n] = s;
        }

        /* ---- main dot accumulation: 8 FFMA2 + 3 LDS.128 per d-pair ---- */
        u64 acc[4][2];
#pragma unroll
        for (int bi = 0; bi < 4; bi++) { acc[bi][0] = 0ull; acc[bi][1] = 0ull; }

        const char* bptr = (const char*)(bp + b0);
        const char* rptr = (const char*)(rp + n0);
#pragma unroll 8
        for (int dp = 0; dp < 64; dp++) {
            ulonglong2 bu01 = *(const ulonglong2*)(bptr);        /* b0,b1 (broadcast) */
            ulonglong2 bu23 = *(const ulonglong2*)(bptr + 16);   /* b2,b3 (broadcast) */
            ulonglong2 ru   = *(const ulonglong2*)(rptr);        /* n0,n0+1 */
            acc[0][0] = ffma2(bu01.x, ru.x, acc[0][0]);
            acc[0][1] = ffma2(bu01.x, ru.y, acc[0][1]);
            acc[1][0] = ffma2(bu01.y, ru.x, acc[1][0]);
            acc[1][1] = ffma2(bu01.y, ru.y, acc[1][1]);
            acc[2][0] = ffma2(bu23.x, ru.x, acc[2][0]);
            acc[2][1] = ffma2(bu23.x, ru.y, acc[2][1]);
            acc[3][0] = ffma2(bu23.y, ru.x, acc[3][0]);
            acc[3][1] = ffma2(bu23.y, ru.y, acc[3][1]);
            bptr += 32 * 8;
            rptr += P2 * 8;
        }
        __syncthreads();   /* npart complete, rp reads complete */
        if (t < 64) normsh[t] = npart[t] + npart[64 + t] + npart[128 + t] + npart[192 + t];
        __syncthreads();   /* normsh ready */

        /* ---- key = ||r||^2 - 2 a.r ; per-lane sorted top-5 per b ---- */
#pragma unroll
        for (int nj = 0; nj < 2; nj++) {
            float nn = normsh[n0 + nj];
            int ng = tb + n0 + nj;
#pragma unroll
            for (int bi = 0; bi < 4; bi++) {
                float key = nn - 2.0f * f2sum(acc[bi][nj]);
                if (key < tk[bi][4]) {
                    tk[bi][4] = key; tn[bi][4] = ng;
#pragma unroll
                    for (int j = 4; j > 0; j--) {
                        if (tk[bi][j] < tk[bi][j - 1]) {
                            float fk = tk[bi][j]; tk[bi][j] = tk[bi][j - 1]; tk[bi][j - 1] = fk;
                            int ii = tn[bi][j]; tn[bi][j] = tn[bi][j - 1]; tn[bi][j - 1] = ii;
                        }
                    }
                }
            }
        }
        /* next-tile restage is safe: every thread passed the norm barriers above */
    }

    /* ---- emit candidates ---- */
#pragma unroll
    for (int bi = 0; bi < 4; bi++) {
        int b = b0 + bi;
        int base = (blockIdx.x * B + b) * CAND_PER_B + lane * 5;
#pragma unroll
        for (int j = 0; j < 5; j++) {
            g_ckey[base + j] = tk[bi][j];
            g_cidx[base + j] = tn[bi][j];
        }
    }
}

/* ================= final: merge candidates, softmax, gather actions ================= */
__global__ void final_kernel(const float* __restrict__ actions, float* __restrict__ out) {
    __shared__ float skey[256 * 5];
    __shared__ int   sidx[256 * 5];
    __shared__ float skey2[32 * 5];
    __shared__ int   sidx2[32 * 5];
    int b = blockIdx.x, t = threadIdx.x;

    float tk[5]; int tn[5];
#pragma unroll
    for (int j = 0; j < 5; j++) { tk[j] = 3.0e38f; tn[j] = 0; }

    const int total = GRID_MAIN * CAND_PER_B;
    for (int i = t; i < total; i += 256) {
        int g = i / CAND_PER_B, r = i - g * CAND_PER_B;
        int addr = (g * B + b) * CAND_PER_B + r;
        float key = g_ckey[addr];
        if (key < tk[4]) {
            int idx = g_cidx[addr];
            tk[4] = key; tn[4] = idx;
#pragma unroll
            for (int j = 4; j > 0; j--) {
                if (tk[j] < tk[j - 1]) {
                    float fk = tk[j]; tk[j] = tk[j - 1]; tk[j - 1] = fk;
                    int ii = tn[j]; tn[j] = tn[j - 1]; tn[j - 1] = ii;
                }
            }
        }
    }
#pragma unroll
    for (int j = 0; j < 5; j++) { skey[t * 5 + j] = tk[j]; sidx[t * 5 + j] = tn[j]; }
    __syncthreads();

    /* stage 2: 32 threads each merge 8 lists of 5 */
    if (t < 32) {
        float fk[5]; int fn[5];
#pragma unroll
        for (int j = 0; j < 5; j++) { fk[j] = 3.0e38f; fn[j] = 0; }
        for (int i = t * 40; i < t * 40 + 40; i++) {
            float key = skey[i];
            if (key < fk[4]) {
                int idx = sidx[i];
                fk[4] = key; fn[4] = idx;
#pragma unroll
                for (int j = 4; j > 0; j--) {
                    if (fk[j] < fk[j - 1]) {
                        float a2 = fk[j]; fk[j] = fk[j - 1]; fk[j - 1] = a2;
                        int i2 = fn[j]; fn[j] = fn[j - 1]; fn[j - 1] = i2;
                    }
                }
            }
        }
#pragma unroll
        for (int j = 0; j < 5; j++) { skey2[t * 5 + j] = fk[j]; sidx2[t * 5 + j] = fn[j]; }
    }
    __syncthreads();

    if (t == 0) {
        float fk[5]; int fn[5];
#pragma unroll
        for (int j = 0; j < 5; j++) { fk[j] = 3.0e38f; fn[j] = 0; }
        for (int i = 0; i < 32 * 5; i++) {
            float key = skey2[i];
            if (key < fk[4]) {
                int idx = sidx2[i];
                fk[4] = key; fn[4] = idx;
#pragma unroll
                for (int j = 4; j > 0; j--) {
                    if (fk[j] < fk[j - 1]) {
                        float a2 = fk[j]; fk[j] = fk[j - 1]; fk[j - 1] = a2;
                        int i2 = fn[j]; fn[j] = fn[j - 1]; fn[j - 1] = i2;
                    }
                }
            }
        }
        float an = g_anorm[b];
        float dloc[5];
        float dmin = 3.0e38f;
#pragma unroll
        for (int j = 0; j < KSEL; j++) {
            dloc[j] = sqrtf(fmaxf(an + fk[j], 1e-12f));
            dmin = fminf(dmin, dloc[j]);
        }
        float wsum = 0.f;
        float pred[ADIM];
#pragma unroll
        for (int a = 0; a < ADIM; a++) pred[a] = 0.f;
#pragma unroll
        for (int j = 0; j < KSEL; j++) {
            float wgt = expf(-(dloc[j] - dmin));
            wsum += wgt;
            const float* arow = actions + (size_t)fn[j] * ADIM;
#pragma unroll
            for (int a = 0; a < ADIM; a++) pred[a] = fmaf(wgt, arow[a], pred[a]);
        }
        float inv = 1.0f / wsum;
#pragma unroll
        for (int a = 0; a < ADIM; a++) out[b * ADIM + a] = pred[a] * inv;
    }
}

/* ================= launch ================= */
extern "C" void kernel_launch(void* const* d_in, const int* in_sizes, int n_in,
                              void* d_out, int out_size) {
    (void)in_sizes; (void)n_in; (void)out_size;
    const float* x       = (const float*)d_in[0];
    const float* W       = (const float*)d_in[1];
    const float* bias    = (const float*)d_in[2];
    const float* reps    = (const float*)d_in[3];
    const float* actions = (const float*)d_in[4];
    float* out = (float*)d_out;

    const int smem_bytes = 64 * P2 * 8 + 64 * 32 * 8 + 4 * 64 * 4 + 64 * 4; /* 51456 */
    cudaFuncSetAttribute(dist_kernel, cudaFuncAttributeMaxDynamicSharedMemorySize, smem_bytes);

    enc_kernel<<<B, 128>>>(x, W, bias);
    dist_kernel<<<GRID_MAIN, 256, smem_bytes>>>(reps);
    final_kernel<<<B, 256>>>(actions, out);
}

// round 3
// speedup vs baseline: 1.5316x; 1.5304x over previous
#include <cuda_runtime.h>
#include <math.h>

#define B 32
#define DIN 2048
#define D 128
#define NREPS 400000
#define ADIM 7
#define KSEL 5

#define GRID_MAIN 296
#define TILE_N 128
#define NTILES (NREPS / TILE_N)   /* 3125, exact */
#define CAND_PER_B 160            /* 32 lanes * 5 */
#define ENC_CHUNKS 16

/* smem layout (bytes) */
#define RP_OFF   0
#define RP_BYTES (64 * 1024)      /* 64 dp-rows x 64 chunks x 16B, XOR-swizzled */
#define BP_OFF   RP_BYTES
#define BP_BYTES (64 * 32 * 8)    /* bp[dp][b] float2 */
#define NORM_OFF (BP_OFF + BP_BYTES)
#define SMEM_TOTAL (NORM_OFF + TILE_N * 4)

typedef unsigned long long u64;

/* ---------------- device scratch ---------------- */
__device__ float g_enc_part[ENC_CHUNKS][B][D];
__device__ float g_batch[B * D];
__device__ float g_anorm[B];
__device__ float g_ckey[GRID_MAIN * B * CAND_PER_B];
__device__ int   g_cidx[GRID_MAIN * B * CAND_PER_B];

/* ---------------- packed f32x2 helpers ---------------- */
__device__ __forceinline__ u64 ffma2(u64 a, u64 b, u64 c) {
    u64 d;
    asm("fma.rn.f32x2 %0, %1, %2, %3;" : "=l"(d) : "l"(a), "l"(b), "l"(c));
    return d;
}
__device__ __forceinline__ float f2sum(u64 p) {
    float lo, hi;
    asm("mov.b64 {%0, %1}, %2;" : "=f"(lo), "=f"(hi) : "l"(p));
    return lo + hi;
}

/* ================= encoder split-K partial ================= */
__global__ void enc_partial(const float* __restrict__ x,
                            const float* __restrict__ W) {
    __shared__ float xs[128];
    int b = blockIdx.x, c = blockIdx.y, t = threadIdx.x;  /* 128 threads */
    xs[t] = x[b * DIN + c * 128 + t];
    __syncthreads();
    const float* Wp = W + (c * 128) * D + t;
    float a0 = 0.f, a1 = 0.f, a2 = 0.f, a3 = 0.f;
#pragma unroll
    for (int k = 0; k < 128; k += 4) {
        a0 = fmaf(xs[k + 0], Wp[(k + 0) * D], a0);
        a1 = fmaf(xs[k + 1], Wp[(k + 1) * D], a1);
        a2 = fmaf(xs[k + 2], Wp[(k + 2) * D], a2);
        a3 = fmaf(xs[k + 3], Wp[(k + 3) * D], a3);
    }
    g_enc_part[c][b][t] = (a0 + a1) + (a2 + a3);
}

/* ================= encoder reduce + norms ================= */
__global__ void enc_reduce(const float* __restrict__ bias) {
    __shared__ float red[4];
    int b = blockIdx.x, t = threadIdx.x;  /* 128 threads */
    float s = bias[t];
#pragma unroll
    for (int c = 0; c < ENC_CHUNKS; c++) s += g_enc_part[c][b][t];
    g_batch[b * D + t] = s;
    float sq = s * s;
#pragma unroll
    for (int o = 16; o > 0; o >>= 1) sq += __shfl_down_sync(0xffffffffu, sq, o);
    if ((t & 31) == 0) red[t >> 5] = sq;
    __syncthreads();
    if (t == 0) g_anorm[b] = red[0] + red[1] + red[2] + red[3];
}

/* ================= main distance kernel ================= */
/* layout: rp chunk (16B) holds f32x2 of rows (2p, 2p+1) for d-pair dp.
   phys byte = dp*1024 + ((p ^ (dp&7)) << 4).  Conflict-free for:
   - staging STS.128 (lane-distinct dp, fixed p)
   - compute LDS.128 (lane-distinct p=lane / 32+lane, fixed dp)            */
__global__ void __launch_bounds__(256, 2) dist_kernel(const float* __restrict__ reps) {
    extern __shared__ char smem[];
    char*  rp     = smem + RP_OFF;
    char*  bpc    = smem + BP_OFF;
    float* normsh = (float*)(smem + NORM_OFF);

    int t = threadIdx.x;
    int w = t >> 5, lane = t & 31;
    int b0 = w * 4;                 /* warp owns batches b0..b0+3 */

    /* pack batch_rep: bp[dp][b] = (batch[b][2dp], batch[b][2dp+1]) */
    for (int i = t; i < 64 * 32; i += 256) {
        int dp = i >> 5, b = i & 31;
        *(float2*)(bpc + dp * 256 + b * 8) =
            make_float2(g_batch[b * D + 2 * dp], g_batch[b * D + 2 * dp + 1]);
    }

    /* precompute swizzled chunk offsets for dp%8 = s */
    int off[8];
#pragma unroll
    for (int s = 0; s < 8; s++) off[s] = s * 1024 + ((lane ^ s) << 4);

    float tk[4][5]; int tn[4][5];
#pragma unroll
    for (int bi = 0; bi < 4; bi++)
#pragma unroll
        for (int j = 0; j < 5; j++) { tk[bi][j] = 3.0e38f; tn[bi][j] = 0; }

    const float2* reps2 = (const float2*)reps;

    __syncthreads();   /* bp ready */

    for (int tile = blockIdx.x; tile < NTILES; tile += GRID_MAIN) {
        int tb = tile * TILE_N;

        /* ---- stage tile (swizzled) + row norms from registers ---- */
#pragma unroll
        for (int pi = 0; pi < 8; pi++) {
            int p = w * 8 + pi;          /* chunk (row-pair) 0..63 */
            int r = tb + 2 * p;
            float2 a00 = reps2[(size_t)r * 64 + lane];            /* row r,   dp=lane    */
            float2 a10 = reps2[(size_t)(r + 1) * 64 + lane];      /* row r+1, dp=lane    */
            float2 a01 = reps2[(size_t)r * 64 + 32 + lane];       /* row r,   dp=32+lane */
            float2 a11 = reps2[(size_t)(r + 1) * 64 + 32 + lane]; /* row r+1, dp=32+lane */
            *(float4*)(rp + lane * 1024 + ((p ^ (lane & 7)) << 4)) =
                make_float4(a00.x, a00.y, a10.x, a10.y);
            *(float4*)(rp + (32 + lane) * 1024 + ((p ^ (lane & 7)) << 4)) =
                make_float4(a01.x, a01.y, a11.x, a11.y);
            float s0 = fmaf(a00.x, a00.x, fmaf(a00.y, a00.y,
                       fmaf(a01.x, a01.x, a01.y * a01.y)));
            float s1 = fmaf(a10.x, a10.x, fmaf(a10.y, a10.y,
                       fmaf(a11.x, a11.x, a11.y * a11.y)));
#pragma unroll
            for (int o = 16; o > 0; o >>= 1) {
                s0 += __shfl_xor_sync(0xffffffffu, s0, o);
                s1 += __shfl_xor_sync(0xffffffffu, s1, o);
            }
            if (lane == 0) *(float2*)(normsh + 2 * p) = make_float2(s0, s1);
        }
        __syncthreads();   /* tile + norms ready */

        /* ---- 4b x 4n register tile; 16 FFMA2 + 4 LDS.128 per dp ---- */
        u64 acc[4][4];
#pragma unroll
        for (int bi = 0; bi < 4; bi++)
#pragma unroll
            for (int nj = 0; nj < 4; nj++) acc[bi][nj] = 0ull;

        const char* bptr = bpc + b0 * 8;
        const char* rbase = rp;
#pragma unroll 1
        for (int g = 0; g < 8; g++) {
#pragma unroll
            for (int s = 0; s < 8; s++) {
                ulonglong2 ru1 = *(const ulonglong2*)(rbase + off[s]);        /* n: 2l, 2l+1     */
                ulonglong2 ru2 = *(const ulonglong2*)(rbase + off[s] + 512);  /* n: 64+2l, 65+2l */
                ulonglong2 bu0 = *(const ulonglong2*)(bptr + s * 256);        /* b0, b0+1        */
                ulonglong2 bu1 = *(const ulonglong2*)(bptr + s * 256 + 16);   /* b0+2, b0+3      */
                acc[0][0] = ffma2(bu0.x, ru1.x, acc[0][0]);
                acc[0][1] = ffma2(bu0.x, ru1.y, acc[0][1]);
                acc[0][2] = ffma2(bu0.x, ru2.x, acc[0][2]);
                acc[0][3] = ffma2(bu0.x, ru2.y, acc[0][3]);
                acc[1][0] = ffma2(bu0.y, ru1.x, acc[1][0]);
                acc[1][1] = ffma2(bu0.y, ru1.y, acc[1][1]);
                acc[1][2] = ffma2(bu0.y, ru2.x, acc[1][2]);
                acc[1][3] = ffma2(bu0.y, ru2.y, acc[1][3]);
                acc[2][0] = ffma2(bu1.x, ru1.x, acc[2][0]);
                acc[2][1] = ffma2(bu1.x, ru1.y, acc[2][1]);
                acc[2][2] = ffma2(bu1.x, ru2.x, acc[2][2]);
                acc[2][3] = ffma2(bu1.x, ru2.y, acc[2][3]);
                acc[3][0] = ffma2(bu1.y, ru1.x, acc[3][0]);
                acc[3][1] = ffma2(bu1.y, ru1.y, acc[3][1]);
                acc[3][2] = ffma2(bu1.y, ru2.x, acc[3][2]);
                acc[3][3] = ffma2(bu1.y, ru2.y, acc[3][3]);
            }
            rbase += 8192;
            bptr  += 8 * 256;
        }

        /* ---- keys + per-lane top-5 per batch ---- */
        float2 nnA = *(const float2*)(normsh + 2 * lane);        /* n: 2l, 2l+1 */
        float2 nnB = *(const float2*)(normsh + 64 + 2 * lane);   /* n: 64+2l, 65+2l */
        float nn[4] = {nnA.x, nnA.y, nnB.x, nnB.y};
        int ng[4] = {tb + 2 * lane, tb + 2 * lane + 1,
                     tb + 64 + 2 * lane, tb + 64 + 2 * lane + 1};
#pragma unroll
        for (int nj = 0; nj < 4; nj++) {
#pragma unroll
            for (int bi = 0; bi < 4; bi++) {
                float key = nn[nj] - 2.0f * f2sum(acc[bi][nj]);
                if (key < tk[bi][4]) {
                    tk[bi][4] = key; tn[bi][4] = ng[nj];
#pragma unroll
                    for (int j = 4; j > 0; j--) {
                        if (tk[bi][j] < tk[bi][j - 1]) {
                            float fk = tk[bi][j]; tk[bi][j] = tk[bi][j - 1]; tk[bi][j - 1] = fk;
                            int ii = tn[bi][j]; tn[bi][j] = tn[bi][j - 1]; tn[bi][j - 1] = ii;
                        }
                    }
                }
            }
        }
        __syncthreads();   /* everyone done reading rp/normsh before restage */
    }

    /* ---- emit candidates ---- */
#pragma unroll
    for (int bi = 0; bi < 4; bi++) {
        int b = b0 + bi;
        int base = (blockIdx.x * B + b) * CAND_PER_B + lane * 5;
#pragma unroll
        for (int j = 0; j < 5; j++) {
            g_ckey[base + j] = tk[bi][j];
            g_cidx[base + j] = tn[bi][j];
        }
    }
}

/* ================= final: merge candidates, softmax, gather actions ================= */
__global__ void final_kernel(const float* __restrict__ actions, float* __restrict__ out) {
    __shared__ float skey[256 * 5];
    __shared__ int   sidx[256 * 5];
    __shared__ float skey2[32 * 5];
    __shared__ int   sidx2[32 * 5];
    int b = blockIdx.x, t = threadIdx.x;

    float tk[5]; int tn[5];
#pragma unroll
    for (int j = 0; j < 5; j++) { tk[j] = 3.0e38f; tn[j] = 0; }

    const int total = GRID_MAIN * CAND_PER_B;
    for (int i = t; i < total; i += 256) {
        int g = i / CAND_PER_B, r = i - g * CAND_PER_B;
        int addr = (g * B + b) * CAND_PER_B + r;
        float key = g_ckey[addr];
        if (key < tk[4]) {
            int idx = g_cidx[addr];
            tk[4] = key; tn[4] = idx;
#pragma unroll
            for (int j = 4; j > 0; j--) {
                if (tk[j] < tk[j - 1]) {
                    float fk = tk[j]; tk[j] = tk[j - 1]; tk[j - 1] = fk;
                    int ii = tn[j]; tn[j] = tn[j - 1]; tn[j - 1] = ii;
                }
            }
        }
    }
#pragma unroll
    for (int j = 0; j < 5; j++) { skey[t * 5 + j] = tk[j]; sidx[t * 5 + j] = tn[j]; }
    __syncthreads();

    if (t < 32) {
        float fk[5]; int fn[5];
#pragma unroll
        for (int j = 0; j < 5; j++) { fk[j] = 3.0e38f; fn[j] = 0; }
        for (int i = t * 40; i < t * 40 + 40; i++) {
            float key = skey[i];
            if (key < fk[4]) {
                int idx = sidx[i];
                fk[4] = key; fn[4] = idx;
#pragma unroll
                for (int j = 4; j > 0; j--) {
                    if (fk[j] < fk[j - 1]) {
                        float a2 = fk[j]; fk[j] = fk[j - 1]; fk[j - 1] = a2;
                        int i2 = fn[j]; fn[j] = fn[j - 1]; fn[j - 1] = i2;
                    }
                }
            }
        }
#pragma unroll
        for (int j = 0; j < 5; j++) { skey2[t * 5 + j] = fk[j]; sidx2[t * 5 + j] = fn[j]; }
    }
    __syncthreads();

    if (t == 0) {
        float fk[5]; int fn[5];
#pragma unroll
        for (int j = 0; j < 5; j++) { fk[j] = 3.0e38f; fn[j] = 0; }
        for (int i = 0; i < 32 * 5; i++) {
            float key = skey2[i];
            if (key < fk[4]) {
                int idx = sidx2[i];
                fk[4] = key; fn[4] = idx;
#pragma unroll
                for (int j = 4; j > 0; j--) {
                    if (fk[j] < fk[j - 1]) {
                        float a2 = fk[j]; fk[j] = fk[j - 1]; fk[j - 1] = a2;
                        int i2 = fn[j]; fn[j] = fn[j - 1]; fn[j - 1] = i2;
                    }
                }
            }
        }
        float an = g_anorm[b];
        float dloc[KSEL];
        float dmin = 3.0e38f;
#pragma unroll
        for (int j = 0; j < KSEL; j++) {
            dloc[j] = sqrtf(fmaxf(an + fk[j], 1e-12f));
            dmin = fminf(dmin, dloc[j]);
        }
        float wsum = 0.f;
        float pred[ADIM];
#pragma unroll
        for (int a = 0; a < ADIM; a++) pred[a] = 0.f;
#pragma unroll
        for (int j = 0; j < KSEL; j++) {
            float wgt = expf(-(dloc[j] - dmin));
            wsum += wgt;
            const float* arow = actions + (size_t)fn[j] * ADIM;
#pragma unroll
            for (int a = 0; a < ADIM; a++) pred[a] = fmaf(wgt, arow[a], pred[a]);
        }
        float inv = 1.0f / wsum;
#pragma unroll
        for (int a = 0; a < ADIM; a++) out[b * ADIM + a] = pred[a] * inv;
    }
}

/* ================= launch ================= */
extern "C" void kernel_launch(void* const* d_in, const int* in_sizes, int n_in,
                              void* d_out, int out_size) {
    (void)in_sizes; (void)n_in; (void)out_size;
    const float* x       = (const float*)d_in[0];
    const float* W       = (const float*)d_in[1];
    const float* bias    = (const float*)d_in[2];
    const float* reps    = (const float*)d_in[3];
    const float* actions = (const float*)d_in[4];
    float* out = (float*)d_out;

    cudaFuncSetAttribute(dist_kernel, cudaFuncAttributeMaxDynamicSharedMemorySize, SMEM_TOTAL);

    enc_partial<<<dim3(B, ENC_CHUNKS), 128>>>(x, W);
    enc_reduce<<<B, 128>>>(bias);
    dist_kernel<<<GRID_MAIN, 256, SMEM_TOTAL>>>(reps);
    final_kernel<<<B, 256>>>(actions, out);
}

// round 4
// speedup vs baseline: 2.2440x; 1.4651x over previous
#include <cuda_runtime.h>
#include <math.h>

#define B 32
#define DIN 2048
#define D 128
#define NREPS 400000
#define ADIM 7
#define KSEL 5

#define GRID_MAIN 296
#define TILE_N 128
#define NTILES (NREPS / TILE_N)   /* 3125, exact */
#define ENC_CHUNKS 16

/* smem layout (bytes) */
#define RP_OFF   0
#define RP_BYTES (64 * 1024)      /* 64 dp-rows x 64 chunks x 16B, XOR-swizzled */
#define BP_OFF   RP_BYTES
#define BP_BYTES (64 * 32 * 8)    /* bp[dp][b] float2 */
#define NORM_OFF (BP_OFF + BP_BYTES)
#define SMEM_TOTAL (NORM_OFF + TILE_N * 4)

typedef unsigned long long u64;

/* ---------------- device scratch ---------------- */
__device__ float g_enc_part[ENC_CHUNKS][B][D];
__device__ float g_batch[B * D];
__device__ float g_anorm[B];
/* batch-major candidate store: [b][block][j] -> contiguous reads in final */
__device__ float g_ckey[B * GRID_MAIN * KSEL];
__device__ int   g_cidx[B * GRID_MAIN * KSEL];

/* ---------------- packed f32x2 helpers ---------------- */
__device__ __forceinline__ u64 ffma2(u64 a, u64 b, u64 c) {
    u64 d;
    asm("fma.rn.f32x2 %0, %1, %2, %3;" : "=l"(d) : "l"(a), "l"(b), "l"(c));
    return d;
}
__device__ __forceinline__ float f2sum(u64 p) {
    float lo, hi;
    asm("mov.b64 {%0, %1}, %2;" : "=f"(lo), "=f"(hi) : "l"(p));
    return lo + hi;
}

/* ================= encoder split-K partial ================= */
__global__ void enc_partial(const float* __restrict__ x,
                            const float* __restrict__ W) {
    __shared__ float xs[128];
    int b = blockIdx.x, c = blockIdx.y, t = threadIdx.x;  /* 128 threads */
    xs[t] = x[b * DIN + c * 128 + t];
    __syncthreads();
    const float* Wp = W + (c * 128) * D + t;
    float a0 = 0.f, a1 = 0.f, a2 = 0.f, a3 = 0.f;
#pragma unroll
    for (int k = 0; k < 128; k += 4) {
        a0 = fmaf(xs[k + 0], Wp[(k + 0) * D], a0);
        a1 = fmaf(xs[k + 1], Wp[(k + 1) * D], a1);
        a2 = fmaf(xs[k + 2], Wp[(k + 2) * D], a2);
        a3 = fmaf(xs[k + 3], Wp[(k + 3) * D], a3);
    }
    g_enc_part[c][b][t] = (a0 + a1) + (a2 + a3);
}

/* ================= encoder reduce + norms ================= */
__global__ void enc_reduce(const float* __restrict__ bias) {
    __shared__ float red[4];
    int b = blockIdx.x, t = threadIdx.x;  /* 128 threads */
    float s = bias[t];
#pragma unroll
    for (int c = 0; c < ENC_CHUNKS; c++) s += g_enc_part[c][b][t];
    g_batch[b * D + t] = s;
    float sq = s * s;
#pragma unroll
    for (int o = 16; o > 0; o >>= 1) sq += __shfl_down_sync(0xffffffffu, sq, o);
    if ((t & 31) == 0) red[t >> 5] = sq;
    __syncthreads();
    if (t == 0) g_anorm[b] = red[0] + red[1] + red[2] + red[3];
}

/* ================= main distance kernel ================= */
/* layout: rp chunk (16B) holds f32x2 of rows (2p, 2p+1) for d-pair dp.
   phys byte = dp*1024 + ((p ^ (dp&7)) << 4).  Conflict-free for:
   - staging STS.128 (lane-distinct dp, fixed p)
   - compute LDS.128 (lane-distinct p=lane / 32+lane, fixed dp)            */
__global__ void __launch_bounds__(256, 2) dist_kernel(const float* __restrict__ reps) {
    extern __shared__ char smem[];
    char*  rp     = smem + RP_OFF;
    char*  bpc    = smem + BP_OFF;
    float* normsh = (float*)(smem + NORM_OFF);

    int t = threadIdx.x;
    int w = t >> 5, lane = t & 31;
    int b0 = w * 4;                 /* warp owns batches b0..b0+3 */

    /* pack batch_rep: bp[dp][b] = (batch[b][2dp], batch[b][2dp+1]) */
    for (int i = t; i < 64 * 32; i += 256) {
        int dp = i >> 5, b = i & 31;
        *(float2*)(bpc + dp * 256 + b * 8) =
            make_float2(g_batch[b * D + 2 * dp], g_batch[b * D + 2 * dp + 1]);
    }

    /* precompute swizzled chunk offsets for dp%8 = s */
    int off[8];
#pragma unroll
    for (int s = 0; s < 8; s++) off[s] = s * 1024 + ((lane ^ s) << 4);

    float tk[4][5]; int tn[4][5];
#pragma unroll
    for (int bi = 0; bi < 4; bi++)
#pragma unroll
        for (int j = 0; j < 5; j++) { tk[bi][j] = 3.0e38f; tn[bi][j] = 0; }

    const float2* reps2 = (const float2*)reps;

    __syncthreads();   /* bp ready */

    for (int tile = blockIdx.x; tile < NTILES; tile += GRID_MAIN) {
        int tb = tile * TILE_N;

        /* ---- stage tile (swizzled) + row norms from registers ---- */
#pragma unroll
        for (int pi = 0; pi < 8; pi++) {
            int p = w * 8 + pi;          /* chunk (row-pair) 0..63 */
            int r = tb + 2 * p;
            float2 a00 = reps2[(size_t)r * 64 + lane];            /* row r,   dp=lane    */
            float2 a10 = reps2[(size_t)(r + 1) * 64 + lane];      /* row r+1, dp=lane    */
            float2 a01 = reps2[(size_t)r * 64 + 32 + lane];       /* row r,   dp=32+lane */
            float2 a11 = reps2[(size_t)(r + 1) * 64 + 32 + lane]; /* row r+1, dp=32+lane */
            *(float4*)(rp + lane * 1024 + ((p ^ (lane & 7)) << 4)) =
                make_float4(a00.x, a00.y, a10.x, a10.y);
            *(float4*)(rp + (32 + lane) * 1024 + ((p ^ (lane & 7)) << 4)) =
                make_float4(a01.x, a01.y, a11.x, a11.y);
            float s0 = fmaf(a00.x, a00.x, fmaf(a00.y, a00.y,
                       fmaf(a01.x, a01.x, a01.y * a01.y)));
            float s1 = fmaf(a10.x, a10.x, fmaf(a10.y, a10.y,
                       fmaf(a11.x, a11.x, a11.y * a11.y)));
#pragma unroll
            for (int o = 16; o > 0; o >>= 1) {
                s0 += __shfl_xor_sync(0xffffffffu, s0, o);
                s1 += __shfl_xor_sync(0xffffffffu, s1, o);
            }
            if (lane == 0) *(float2*)(normsh + 2 * p) = make_float2(s0, s1);
        }
        __syncthreads();   /* tile + norms ready */

        /* ---- 4b x 4n register tile; 16 FFMA2 + 4 LDS.128 per dp ---- */
        u64 acc[4][4];
#pragma unroll
        for (int bi = 0; bi < 4; bi++)
#pragma unroll
            for (int nj = 0; nj < 4; nj++) acc[bi][nj] = 0ull;

        const char* bptr = bpc + b0 * 8;
        const char* rbase = rp;
#pragma unroll 1
        for (int g = 0; g < 8; g++) {
#pragma unroll
            for (int s = 0; s < 8; s++) {
                ulonglong2 ru1 = *(const ulonglong2*)(rbase + off[s]);        /* n: 2l, 2l+1     */
                ulonglong2 ru2 = *(const ulonglong2*)(rbase + off[s] + 512);  /* n: 64+2l, 65+2l */
                ulonglong2 bu0 = *(const ulonglong2*)(bptr + s * 256);        /* b0, b0+1        */
                ulonglong2 bu1 = *(const ulonglong2*)(bptr + s * 256 + 16);   /* b0+2, b0+3      */
                acc[0][0] = ffma2(bu0.x, ru1.x, acc[0][0]);
                acc[0][1] = ffma2(bu0.x, ru1.y, acc[0][1]);
                acc[0][2] = ffma2(bu0.x, ru2.x, acc[0][2]);
                acc[0][3] = ffma2(bu0.x, ru2.y, acc[0][3]);
                acc[1][0] = ffma2(bu0.y, ru1.x, acc[1][0]);
                acc[1][1] = ffma2(bu0.y, ru1.y, acc[1][1]);
                acc[1][2] = ffma2(bu0.y, ru2.x, acc[1][2]);
                acc[1][3] = ffma2(bu0.y, ru2.y, acc[1][3]);
                acc[2][0] = ffma2(bu1.x, ru1.x, acc[2][0]);
                acc[2][1] = ffma2(bu1.x, ru1.y, acc[2][1]);
                acc[2][2] = ffma2(bu1.x, ru2.x, acc[2][2]);
                acc[2][3] = ffma2(bu1.x, ru2.y, acc[2][3]);
                acc[3][0] = ffma2(bu1.y, ru1.x, acc[3][0]);
                acc[3][1] = ffma2(bu1.y, ru1.y, acc[3][1]);
                acc[3][2] = ffma2(bu1.y, ru2.x, acc[3][2]);
                acc[3][3] = ffma2(bu1.y, ru2.y, acc[3][3]);
            }
            rbase += 8192;
            bptr  += 8 * 256;
        }

        /* ---- keys + per-lane top-5 per batch ---- */
        float2 nnA = *(const float2*)(normsh + 2 * lane);        /* n: 2l, 2l+1 */
        float2 nnB = *(const float2*)(normsh + 64 + 2 * lane);   /* n: 64+2l, 65+2l */
        float nn[4] = {nnA.x, nnA.y, nnB.x, nnB.y};
        int ng[4] = {tb + 2 * lane, tb + 2 * lane + 1,
                     tb + 64 + 2 * lane, tb + 64 + 2 * lane + 1};
#pragma unroll
        for (int nj = 0; nj < 4; nj++) {
#pragma unroll
            for (int bi = 0; bi < 4; bi++) {
                float key = nn[nj] - 2.0f * f2sum(acc[bi][nj]);
                if (key < tk[bi][4]) {
                    tk[bi][4] = key; tn[bi][4] = ng[nj];
#pragma unroll
                    for (int j = 4; j > 0; j--) {
                        if (tk[bi][j] < tk[bi][j - 1]) {
                            float fk = tk[bi][j]; tk[bi][j] = tk[bi][j - 1]; tk[bi][j - 1] = fk;
                            int ii = tn[bi][j]; tn[bi][j] = tn[bi][j - 1]; tn[bi][j - 1] = ii;
                        }
                    }
                }
            }
        }
        __syncthreads();   /* everyone done reading rp/normsh before restage */
    }

    /* ---- warp-level merge: 32 sorted 5-lists -> 1 sorted 5-list per batch ---- */
#pragma unroll
    for (int bi = 0; bi < 4; bi++) {
#pragma unroll
        for (int o = 16; o > 0; o >>= 1) {
            float ok[5]; int on[5];
#pragma unroll
            for (int j = 0; j < 5; j++) {
                ok[j] = __shfl_xor_sync(0xffffffffu, tk[bi][j], o);
                on[j] = __shfl_xor_sync(0xffffffffu, tn[bi][j], o);
            }
#pragma unroll
            for (int j = 0; j < 5; j++) {
                float key = ok[j]; int idx = on[j];
                if (key < tk[bi][4]) {
                    tk[bi][4] = key; tn[bi][4] = idx;
#pragma unroll
                    for (int m = 4; m > 0; m--) {
                        if (tk[bi][m] < tk[bi][m - 1]) {
                            float fk = tk[bi][m]; tk[bi][m] = tk[bi][m - 1]; tk[bi][m - 1] = fk;
                            int ii = tn[bi][m]; tn[bi][m] = tn[bi][m - 1]; tn[bi][m - 1] = ii;
                        }
                    }
                }
            }
        }
        if (lane == 0) {
            int base = ((b0 + bi) * GRID_MAIN + blockIdx.x) * KSEL;
#pragma unroll
            for (int j = 0; j < 5; j++) {
                g_ckey[base + j] = tk[bi][j];
                g_cidx[base + j] = tn[bi][j];
            }
        }
    }
}

/* ================= final: merge 1480 candidates/batch, softmax, gather ================= */
__global__ void final_kernel(const float* __restrict__ actions, float* __restrict__ out) {
    int b = blockIdx.x, lane = threadIdx.x;  /* 32 threads */

    float tk[5]; int tn[5];
#pragma unroll
    for (int j = 0; j < 5; j++) { tk[j] = 3.0e38f; tn[j] = 0; }

    const int total = GRID_MAIN * KSEL;   /* 1480, contiguous per batch */
    const float* ck = g_ckey + b * total;
    const int*   ci = g_cidx + b * total;
    for (int i = lane; i < total; i += 32) {
        float key = ck[i];
        if (key < tk[4]) {
            int idx = ci[i];
            tk[4] = key; tn[4] = idx;
#pragma unroll
            for (int j = 4; j > 0; j--) {
                if (tk[j] < tk[j - 1]) {
                    float fk = tk[j]; tk[j] = tk[j - 1]; tk[j - 1] = fk;
                    int ii = tn[j]; tn[j] = tn[j - 1]; tn[j - 1] = ii;
                }
            }
        }
    }

    /* shuffle merge across the warp */
#pragma unroll
    for (int o = 16; o > 0; o >>= 1) {
        float ok[5]; int on[5];
#pragma unroll
        for (int j = 0; j < 5; j++) {
            ok[j] = __shfl_xor_sync(0xffffffffu, tk[j], o);
            on[j] = __shfl_xor_sync(0xffffffffu, tn[j], o);
        }
#pragma unroll
        for (int j = 0; j < 5; j++) {
            float key = ok[j]; int idx = on[j];
            if (key < tk[4]) {
                tk[4] = key; tn[4] = idx;
#pragma unroll
                for (int m = 4; m > 0; m--) {
                    if (tk[m] < tk[m - 1]) {
                        float fk = tk[m]; tk[m] = tk[m - 1]; tk[m - 1] = fk;
                        int ii = tn[m]; tn[m] = tn[m - 1]; tn[m - 1] = ii;
                    }
                }
            }
        }
    }

    if (lane == 0) {
        float an = g_anorm[b];
        float dloc[KSEL];
        float dmin = 3.0e38f;
#pragma unroll
        for (int j = 0; j < KSEL; j++) {
            dloc[j] = sqrtf(fmaxf(an + tk[j], 1e-12f));
            dmin = fminf(dmin, dloc[j]);
        }
        float wsum = 0.f;
        float pred[ADIM];
#pragma unroll
        for (int a = 0; a < ADIM; a++) pred[a] = 0.f;
#pragma unroll
        for (int j = 0; j < KSEL; j++) {
            float wgt = expf(-(dloc[j] - dmin));
            wsum += wgt;
            const float* arow = actions + (size_t)tn[j] * ADIM;
#pragma unroll
            for (int a = 0; a < ADIM; a++) pred[a] = fmaf(wgt, arow[a], pred[a]);
        }
        float inv = 1.0f / wsum;
#pragma unroll
        for (int a = 0; a < ADIM; a++) out[b * ADIM + a] = pred[a] * inv;
    }
}

/* ================= launch ================= */
extern "C" void kernel_launch(void* const* d_in, const int* in_sizes, int n_in,
                              void* d_out, int out_size) {
    (void)in_sizes; (void)n_in; (void)out_size;
    const float* x       = (const float*)d_in[0];
    const float* W       = (const float*)d_in[1];
    const float* bias    = (const float*)d_in[2];
    const float* reps    = (const float*)d_in[3];
    const float* actions = (const float*)d_in[4];
    float* out = (float*)d_out;

    cudaFuncSetAttribute(dist_kernel, cudaFuncAttributeMaxDynamicSharedMemorySize, SMEM_TOTAL);

    enc_partial<<<dim3(B, ENC_CHUNKS), 128>>>(x, W);
    enc_reduce<<<B, 128>>>(bias);
    dist_kernel<<<GRID_MAIN, 256, SMEM_TOTAL>>>(reps);
    final_kernel<<<B, 32>>>(actions, out);
}

// round 5
// speedup vs baseline: 2.4788x; 1.1046x over previous
#include <cuda_runtime.h>
#include <math.h>

#define B 32
#define DIN 2048
#define D 128
#define NREPS 400000
#define ADIM 7
#define KSEL 5

#define GRID_MAIN 296
#define TILE_N 128
#define NTILES (NREPS / TILE_N)   /* 3125, exact */
#define ENC_CHUNKS 16

/* smem layout (bytes) */
#define RP_OFF   0
#define RP_BYTES (64 * 1024)      /* 64 dp-rows x 64 chunks x 16B, XOR-swizzled */
#define BP_OFF   RP_BYTES
#define BP_BYTES (64 * 32 * 8)    /* bp[dp][b] float2 */
#define NORM_OFF (BP_OFF + BP_BYTES)
#define SMEM_TOTAL (NORM_OFF + TILE_N * 4)

typedef unsigned long long u64;

/* ---------------- device scratch ---------------- */
__device__ float g_enc_part[ENC_CHUNKS][B][D];
__device__ float g_batch[B * D];
__device__ float g_anorm[B];
/* batch-major candidate store: [b][block][j] -> contiguous reads in final */
__device__ float g_ckey[B * GRID_MAIN * KSEL];
__device__ int   g_cidx[B * GRID_MAIN * KSEL];

/* ---------------- packed f32x2 helpers ---------------- */
__device__ __forceinline__ u64 ffma2(u64 a, u64 b, u64 c) {
    u64 d;
    asm("fma.rn.f32x2 %0, %1, %2, %3;" : "=l"(d) : "l"(a), "l"(b), "l"(c));
    return d;
}
__device__ __forceinline__ float f2sum(u64 p) {
    float lo, hi;
    asm("mov.b64 {%0, %1}, %2;" : "=f"(lo), "=f"(hi) : "l"(p));
    return lo + hi;
}

/* ================= encoder split-K partial ================= */
__global__ void enc_partial(const float* __restrict__ x,
                            const float* __restrict__ W) {
    __shared__ float xs[128];
    int b = blockIdx.x, c = blockIdx.y, t = threadIdx.x;  /* 128 threads */
    xs[t] = x[b * DIN + c * 128 + t];
    __syncthreads();
    const float* Wp = W + (c * 128) * D + t;
    float a0 = 0.f, a1 = 0.f, a2 = 0.f, a3 = 0.f;
#pragma unroll
    for (int k = 0; k < 128; k += 4) {
        a0 = fmaf(xs[k + 0], Wp[(k + 0) * D], a0);
        a1 = fmaf(xs[k + 1], Wp[(k + 1) * D], a1);
        a2 = fmaf(xs[k + 2], Wp[(k + 2) * D], a2);
        a3 = fmaf(xs[k + 3], Wp[(k + 3) * D], a3);
    }
    g_enc_part[c][b][t] = (a0 + a1) + (a2 + a3);
}

/* ================= encoder reduce + norms ================= */
__global__ void enc_reduce(const float* __restrict__ bias) {
    __shared__ float red[4];
    int b = blockIdx.x, t = threadIdx.x;  /* 128 threads */
    float s = bias[t];
#pragma unroll
    for (int c = 0; c < ENC_CHUNKS; c++) s += g_enc_part[c][b][t];
    g_batch[b * D + t] = s;
    float sq = s * s;
#pragma unroll
    for (int o = 16; o > 0; o >>= 1) sq += __shfl_down_sync(0xffffffffu, sq, o);
    if ((t & 31) == 0) red[t >> 5] = sq;
    __syncthreads();
    if (t == 0) g_anorm[b] = red[0] + red[1] + red[2] + red[3];
}

/* ================= main distance kernel ================= */
/* layout: rp chunk (16B) holds f32x2 of rows (2p, 2p+1) for d-pair dp.
   phys byte = dp*1024 + ((p ^ (dp&7)) << 4).  Conflict-free for:
   - staging STS.128 (lane-distinct dp, fixed p)
   - compute LDS.128 (lane-distinct p=lane / 32+lane, fixed dp)            */
__global__ void __launch_bounds__(256, 2) dist_kernel(const float* __restrict__ reps) {
    extern __shared__ char smem[];
    char*  rp     = smem + RP_OFF;
    char*  bpc    = smem + BP_OFF;
    float* normsh = (float*)(smem + NORM_OFF);

    int t = threadIdx.x;
    int w = t >> 5, lane = t & 31;
    int b0 = w * 4;                 /* warp owns batches b0..b0+3 */

    /* pack batch_rep: bp[dp][b] = (batch[b][2dp], batch[b][2dp+1]) */
    for (int i = t; i < 64 * 32; i += 256) {
        int dp = i >> 5, b = i & 31;
        *(float2*)(bpc + dp * 256 + b * 8) =
            make_float2(g_batch[b * D + 2 * dp], g_batch[b * D + 2 * dp + 1]);
    }

    /* precompute swizzled chunk offsets for dp%8 = s */
    int off[8];
#pragma unroll
    for (int s = 0; s < 8; s++) off[s] = s * 1024 + ((lane ^ s) << 4);

    float tk[4][5]; int tn[4][5];
#pragma unroll
    for (int bi = 0; bi < 4; bi++)
#pragma unroll
        for (int j = 0; j < 5; j++) { tk[bi][j] = 3.0e38f; tn[bi][j] = 0; }

    const float2* reps2 = (const float2*)reps;

    __syncthreads();   /* bp ready */

    for (int tile = blockIdx.x; tile < NTILES; tile += GRID_MAIN) {
        int tb = tile * TILE_N;

        /* ---- stage tile (swizzled) + row norms from registers ---- */
#pragma unroll
        for (int pi = 0; pi < 8; pi++) {
            int p = w * 8 + pi;          /* chunk (row-pair) 0..63 */
            int r = tb + 2 * p;
            float2 a00 = reps2[(size_t)r * 64 + lane];            /* row r,   dp=lane    */
            float2 a10 = reps2[(size_t)(r + 1) * 64 + lane];      /* row r+1, dp=lane    */
            float2 a01 = reps2[(size_t)r * 64 + 32 + lane];       /* row r,   dp=32+lane */
            float2 a11 = reps2[(size_t)(r + 1) * 64 + 32 + lane]; /* row r+1, dp=32+lane */
            *(float4*)(rp + lane * 1024 + ((p ^ (lane & 7)) << 4)) =
                make_float4(a00.x, a00.y, a10.x, a10.y);
            *(float4*)(rp + (32 + lane) * 1024 + ((p ^ (lane & 7)) << 4)) =
                make_float4(a01.x, a01.y, a11.x, a11.y);
            float s0 = fmaf(a00.x, a00.x, fmaf(a00.y, a00.y,
                       fmaf(a01.x, a01.x, a01.y * a01.y)));
            float s1 = fmaf(a10.x, a10.x, fmaf(a10.y, a10.y,
                       fmaf(a11.x, a11.x, a11.y * a11.y)));
#pragma unroll
            for (int o = 16; o > 0; o >>= 1) {
                s0 += __shfl_xor_sync(0xffffffffu, s0, o);
                s1 += __shfl_xor_sync(0xffffffffu, s1, o);
            }
            if (lane == 0) *(float2*)(normsh + 2 * p) = make_float2(s0, s1);
        }
        __syncthreads();   /* tile + norms ready */

        /* ---- 4b x 4n register tile; 16 FFMA2 + 4 LDS.128 per dp ---- */
        u64 acc[4][4];
#pragma unroll
        for (int bi = 0; bi < 4; bi++)
#pragma unroll
            for (int nj = 0; nj < 4; nj++) acc[bi][nj] = 0ull;

        const char* bptr = bpc + b0 * 8;
        const char* rbase = rp;
#pragma unroll 1
        for (int g = 0; g < 8; g++) {
#pragma unroll
            for (int s = 0; s < 8; s++) {
                ulonglong2 ru1 = *(const ulonglong2*)(rbase + off[s]);        /* n: 2l, 2l+1     */
                ulonglong2 ru2 = *(const ulonglong2*)(rbase + off[s] + 512);  /* n: 64+2l, 65+2l */
                ulonglong2 bu0 = *(const ulonglong2*)(bptr + s * 256);        /* b0, b0+1        */
                ulonglong2 bu1 = *(const ulonglong2*)(bptr + s * 256 + 16);   /* b0+2, b0+3      */
                acc[0][0] = ffma2(bu0.x, ru1.x, acc[0][0]);
                acc[0][1] = ffma2(bu0.x, ru1.y, acc[0][1]);
                acc[0][2] = ffma2(bu0.x, ru2.x, acc[0][2]);
                acc[0][3] = ffma2(bu0.x, ru2.y, acc[0][3]);
                acc[1][0] = ffma2(bu0.y, ru1.x, acc[1][0]);
                acc[1][1] = ffma2(bu0.y, ru1.y, acc[1][1]);
                acc[1][2] = ffma2(bu0.y, ru2.x, acc[1][2]);
                acc[1][3] = ffma2(bu0.y, ru2.y, acc[1][3]);
                acc[2][0] = ffma2(bu1.x, ru1.x, acc[2][0]);
                acc[2][1] = ffma2(bu1.x, ru1.y, acc[2][1]);
                acc[2][2] = ffma2(bu1.x, ru2.x, acc[2][2]);
                acc[2][3] = ffma2(bu1.x, ru2.y, acc[2][3]);
                acc[3][0] = ffma2(bu1.y, ru1.x, acc[3][0]);
                acc[3][1] = ffma2(bu1.y, ru1.y, acc[3][1]);
                acc[3][2] = ffma2(bu1.y, ru2.x, acc[3][2]);
                acc[3][3] = ffma2(bu1.y, ru2.y, acc[3][3]);
            }
            rbase += 8192;
            bptr  += 8 * 256;
        }

        /* ---- keys + per-lane top-5 per batch ---- */
        float2 nnA = *(const float2*)(normsh + 2 * lane);        /* n: 2l, 2l+1 */
        float2 nnB = *(const float2*)(normsh + 64 + 2 * lane);   /* n: 64+2l, 65+2l */
        float nn[4] = {nnA.x, nnA.y, nnB.x, nnB.y};
        int ng[4] = {tb + 2 * lane, tb + 2 * lane + 1,
                     tb + 64 + 2 * lane, tb + 64 + 2 * lane + 1};
#pragma unroll
        for (int nj = 0; nj < 4; nj++) {
#pragma unroll
            for (int bi = 0; bi < 4; bi++) {
                float key = nn[nj] - 2.0f * f2sum(acc[bi][nj]);
                if (key < tk[bi][4]) {
                    tk[bi][4] = key; tn[bi][4] = ng[nj];
#pragma unroll
                    for (int j = 4; j > 0; j--) {
                        if (tk[bi][j] < tk[bi][j - 1]) {
                            float fk = tk[bi][j]; tk[bi][j] = tk[bi][j - 1]; tk[bi][j - 1] = fk;
                            int ii = tn[bi][j]; tn[bi][j] = tn[bi][j - 1]; tn[bi][j - 1] = ii;
                        }
                    }
                }
            }
        }
        __syncthreads();   /* everyone done reading rp/normsh before restage */
    }

    /* ---- warp-level merge: 32 sorted 5-lists -> 1 sorted 5-list per batch ---- */
#pragma unroll
    for (int bi = 0; bi < 4; bi++) {
#pragma unroll
        for (int o = 16; o > 0; o >>= 1) {
            float ok[5]; int on[5];
#pragma unroll
            for (int j = 0; j < 5; j++) {
                ok[j] = __shfl_xor_sync(0xffffffffu, tk[bi][j], o);
                on[j] = __shfl_xor_sync(0xffffffffu, tn[bi][j], o);
            }
#pragma unroll
            for (int j = 0; j < 5; j++) {
                float key = ok[j]; int idx = on[j];
                if (key < tk[bi][4]) {
                    tk[bi][4] = key; tn[bi][4] = idx;
#pragma unroll
                    for (int m = 4; m > 0; m--) {
                        if (tk[bi][m] < tk[bi][m - 1]) {
                            float fk = tk[bi][m]; tk[bi][m] = tk[bi][m - 1]; tk[bi][m - 1] = fk;
                            int ii = tn[bi][m]; tn[bi][m] = tn[bi][m - 1]; tn[bi][m - 1] = ii;
                        }
                    }
                }
            }
        }
        if (lane == 0) {
            int base = ((b0 + bi) * GRID_MAIN + blockIdx.x) * KSEL;
#pragma unroll
            for (int j = 0; j < 5; j++) {
                g_ckey[base + j] = tk[bi][j];
                g_cidx[base + j] = tn[bi][j];
            }
        }
    }
}

/* ================= final: merge 1480 candidates/batch, softmax, gather ================= */
__global__ void __launch_bounds__(256) final_kernel(const float* __restrict__ actions,
                                                    float* __restrict__ out) {
    __shared__ float skey[8 * KSEL];
    __shared__ int   sidx[8 * KSEL];
    int b = blockIdx.x, t = threadIdx.x;
    int w = t >> 5, lane = t & 31;

    float tk[5]; int tn[5];
#pragma unroll
    for (int j = 0; j < 5; j++) { tk[j] = 3.0e38f; tn[j] = 0; }

    const int total = GRID_MAIN * KSEL;   /* 1480, contiguous per batch */
    const float* ck = g_ckey + b * total;
    const int*   ci = g_cidx + b * total;
    /* ~6 coalesced strided loads per thread */
    for (int i = t; i < total; i += 256) {
        float key = ck[i];
        if (key < tk[4]) {
            int idx = ci[i];
            tk[4] = key; tn[4] = idx;
#pragma unroll
            for (int j = 4; j > 0; j--) {
                if (tk[j] < tk[j - 1]) {
                    float fk = tk[j]; tk[j] = tk[j - 1]; tk[j - 1] = fk;
                    int ii = tn[j]; tn[j] = tn[j - 1]; tn[j - 1] = ii;
                }
            }
        }
    }

    /* warp shuffle merge */
#pragma unroll
    for (int o = 16; o > 0; o >>= 1) {
        float ok[5]; int on[5];
#pragma unroll
        for (int j = 0; j < 5; j++) {
            ok[j] = __shfl_xor_sync(0xffffffffu, tk[j], o);
            on[j] = __shfl_xor_sync(0xffffffffu, tn[j], o);
        }
#pragma unroll
        for (int j = 0; j < 5; j++) {
            float key = ok[j]; int idx = on[j];
            if (key < tk[4]) {
                tk[4] = key; tn[4] = idx;
#pragma unroll
                for (int m = 4; m > 0; m--) {
                    if (tk[m] < tk[m - 1]) {
                        float fk = tk[m]; tk[m] = tk[m - 1]; tk[m - 1] = fk;
                        int ii = tn[m]; tn[m] = tn[m - 1]; tn[m - 1] = ii;
                    }
                }
            }
        }
    }
    if (lane == 0) {
#pragma unroll
        for (int j = 0; j < 5; j++) { skey[w * KSEL + j] = tk[j]; sidx[w * KSEL + j] = tn[j]; }
    }
    __syncthreads();

    if (t == 0) {
        float fk[5]; int fn[5];
#pragma unroll
        for (int j = 0; j < 5; j++) { fk[j] = skey[j]; fn[j] = sidx[j]; }
        for (int i = KSEL; i < 8 * KSEL; i++) {
            float key = skey[i];
            if (key < fk[4]) {
                int idx = sidx[i];
                fk[4] = key; fn[4] = idx;
#pragma unroll
                for (int m = 4; m > 0; m--) {
                    if (fk[m] < fk[m - 1]) {
                        float a2 = fk[m]; fk[m] = fk[m - 1]; fk[m - 1] = a2;
                        int i2 = fn[m]; fn[m] = fn[m - 1]; fn[m - 1] = i2;
                    }
                }
            }
        }
        float an = g_anorm[b];
        float dloc[KSEL];
        float dmin = 3.0e38f;
#pragma unroll
        for (int j = 0; j < KSEL; j++) {
            dloc[j] = sqrtf(fmaxf(an + fk[j], 1e-12f));
            dmin = fminf(dmin, dloc[j]);
        }
        float wsum = 0.f;
        float pred[ADIM];
#pragma unroll
        for (int a = 0; a < ADIM; a++) pred[a] = 0.f;
#pragma unroll
        for (int j = 0; j < KSEL; j++) {
            float wgt = expf(-(dloc[j] - dmin));
            wsum += wgt;
            const float* arow = actions + (size_t)fn[j] * ADIM;
#pragma unroll
            for (int a = 0; a < ADIM; a++) pred[a] = fmaf(wgt, arow[a], pred[a]);
        }
        float inv = 1.0f / wsum;
#pragma unroll
        for (int a = 0; a < ADIM; a++) out[b * ADIM + a] = pred[a] * inv;
    }
}

/* ================= launch ================= */
extern "C" void kernel_launch(void* const* d_in, const int* in_sizes, int n_in,
                              void* d_out, int out_size) {
    (void)in_sizes; (void)n_in; (void)out_size;
    const float* x       = (const float*)d_in[0];
    const float* W       = (const float*)d_in[1];
    const float* bias    = (const float*)d_in[2];
    const float* reps    = (const float*)d_in[3];
    const float* actions = (const float*)d_in[4];
    float* out = (float*)d_out;

    cudaFuncSetAttribute(dist_kernel, cudaFuncAttributeMaxDynamicSharedMemorySize, SMEM_TOTAL);

    enc_partial<<<dim3(B, ENC_CHUNKS), 128>>>(x, W);
    enc_reduce<<<B, 128>>>(bias);
    dist_kernel<<<GRID_MAIN, 256, SMEM_TOTAL>>>(reps);
    final_kernel<<<B, 256>>>(actions, out);
}